// round 9
// baseline (speedup 1.0000x reference)
#include <cuda_runtime.h>
#include <cuda_bf16.h>
#include <math.h>
#include <cstdint>

// ---------------- problem constants ----------------
#define BATCH   4
#define LSEQ    2305          // 1 global token + 48*48
#define DM      256           // D_MODEL
#define DI      512           // D_INNER
#define DS      16            // D_STATE
#define DTR     16            // DT_RANK
#define NDBL    48            // DTR + 2*D_STATE
#define MROWS   (BATCH*LSEQ)  // 9220
#define CHUNK   128
#define NCHUNK  19            // ceil(2305/128)

// ---------------- scratch (device globals; no allocation allowed) ----------------
__device__ __nv_bfloat16 g_seqh[MROWS*DM];
__device__ __nv_bfloat16 g_seql[MROWS*DM];
__device__ float g_xz  [MROWS*2*DI];
__device__ float g_u   [MROWS*DI];
__device__ float g_xdbl[MROWS*NDBL];
__device__ float g_dt  [MROWS*DI];
__device__ __nv_bfloat16 g_yh[MROWS*DI];
__device__ __nv_bfloat16 g_yl[MROWS*DI];
__device__ float g_P   [BATCH*DI*NCHUNK*DS];
__device__ float g_hf  [BATCH*DI*NCHUNK*DS];
__device__ float g_hin [BATCH*DI*NCHUNK*DS];
// split weights
__device__ __nv_bfloat16 g_wih[2*DI*DM], g_wil[2*DI*DM];   // in_proj 1024x256
__device__ __nv_bfloat16 g_woh[DM*DI],   g_wol[DM*DI];     // out_proj 256x512

// ---------------- math helpers ----------------
__device__ __forceinline__ float siluf(float x) { return x / (1.0f + __expf(-x)); }
__device__ __forceinline__ float softplusf(float x) {
    return fmaxf(x, 0.0f) + log1pf(__expf(-fabsf(x)));
}
__device__ __forceinline__ void split_bf16(float v, __nv_bfloat16& h, __nv_bfloat16& l) {
    h = __float2bfloat16(v);
    l = __float2bfloat16(v - __bfloat162float(h));
}
__device__ __forceinline__ uint32_t smem_u32(const void* p) {
    uint32_t a;
    asm("{ .reg .u64 t; cvta.to.shared.u64 t, %1; cvt.u32.u64 %0, t; }" : "=r"(a) : "l"(p));
    return a;
}
#define CP_ASYNC16(dst, src, nbytes) \
    asm volatile("cp.async.cg.shared.global [%0], [%1], 16, %2;" \
                 :: "r"(dst), "l"(src), "r"(nbytes))
#define CP_COMMIT()  asm volatile("cp.async.commit_group;" ::: "memory")
#define CP_WAIT1()   asm volatile("cp.async.wait_group 1;" ::: "memory")

__device__ __forceinline__ void mma16816(float& c0, float& c1, float& c2, float& c3,
                                         uint32_t a0, uint32_t a1, uint32_t a2, uint32_t a3,
                                         uint32_t b0, uint32_t b1) {
    asm volatile("mma.sync.aligned.m16n8k16.row.col.f32.bf16.bf16.f32 "
                 "{%0,%1,%2,%3}, {%4,%5,%6,%7}, {%8,%9}, {%0,%1,%2,%3};"
                 : "+f"(c0), "+f"(c1), "+f"(c2), "+f"(c3)
                 : "r"(a0), "r"(a1), "r"(a2), "r"(a3), "r"(b0), "r"(b1));
}

// ---------------- 1) build seq (writes bf16 hi/lo) ----------------
__global__ void build_seq_kernel(const float* __restrict__ x,
                                 const float* __restrict__ gtok) {
    int idx = blockIdx.x * blockDim.x + threadIdx.x;
    if (idx >= MROWS * DM) return;
    int c = idx % DM;
    int l = (idx / DM) % LSEQ;
    int b = idx / (DM * LSEQ);
    float v;
    if (l == 0) {
        v = gtok[c];
    } else {
        int lp = l - 1;
        int H2 = lp / 48, W2 = lp % 48;
        int ch = c * 4 + (H2 & 1) * 2 + (W2 & 1);
        v = x[((b * 1024 + ch) * 24 + (H2 >> 1)) * 24 + (W2 >> 1)];
    }
    __nv_bfloat16 h, lo;
    split_bf16(v, h, lo);
    g_seqh[idx] = h; g_seql[idx] = lo;
}

// ---------------- weight hi/lo split ----------------
__global__ void split_kernel(const float* __restrict__ s,
                             __nv_bfloat16* __restrict__ h,
                             __nv_bfloat16* __restrict__ l, int n) {
    int i = blockIdx.x * blockDim.x + threadIdx.x;
    if (i >= n) return;
    __nv_bfloat16 hv, lv;
    split_bf16(s[i], hv, lv);
    h[i] = hv; l[i] = lv;
}

// ---------------- 2) bf16 mma.sync GEMM: C[M,Ntot] = A[M,K] @ W[Ntot,K]^T ----------------
// fp32 emulation via 3 bf16 segments: Ah*Wh + Al*Wh + Ah*Wl.
// CTA tile 128x128, 8 warps (2 m x 4 n), warp tile 64x32, BK=32, cp.async
// double buffering. Smem rows padded to 40 bf16 (80B, 16B aligned, conflict-free).
#define GSTR 40   // padded row stride in bf16 elements

template<bool FUSE_OUT>
__global__ __launch_bounds__(256, 2)
void gemm_mma_kernel(const __nv_bfloat16* __restrict__ Ah,
                     const __nv_bfloat16* __restrict__ Al,
                     const __nv_bfloat16* __restrict__ Wh,
                     const __nv_bfloat16* __restrict__ Wl,
                     float* __restrict__ C, int M, int Ntot, int K) {
    __shared__ __align__(16) __nv_bfloat16 sA[2][128 * GSTR];
    __shared__ __align__(16) __nv_bfloat16 sB[2][128 * GSTR];

    const int tid = threadIdx.x;
    const int wid = tid >> 5;
    const int lane = tid & 31;
    const int gr = lane >> 2;     // 0..7
    const int gc = lane & 3;      // 0..3
    const int wm = wid >> 2;      // 0..1
    const int wn = wid & 3;       // 0..3
    const int m0 = blockIdx.x * 128;
    const int n0 = blockIdx.y * 128;

    const int kseg = K >> 5;      // 32-wide chunks per segment
    const int NC = 3 * kseg;

    float acc[4][4][4];
#pragma unroll
    for (int i = 0; i < 4; i++)
#pragma unroll
        for (int j = 0; j < 4; j++)
#pragma unroll
            for (int q = 0; q < 4; q++) acc[i][j][q] = 0.0f;

    // stage chunk c into buffer buf
    auto stage = [&](int c, int buf) {
        const int seg = c / kseg;
        const int k0 = (c - seg * kseg) * 32;
        const __nv_bfloat16* Asrc = (seg == 1) ? Al : Ah;
        const __nv_bfloat16* Wsrc = (seg == 2) ? Wl : Wh;
#pragma unroll
        for (int q = 0; q < 2; q++) {
            int i = tid * 2 + q;          // 0..511
            int r = i >> 2;               // 0..127
            int s = (i & 3) * 8;          // 0,8,16,24
            uint32_t da = smem_u32(&sA[buf][r * GSTR + s]);
            const __nv_bfloat16* pa = Asrc + (size_t)(m0 + r) * K + k0 + s;
            CP_ASYNC16(da, pa, (m0 + r < M) ? 16 : 0);
            uint32_t db = smem_u32(&sB[buf][r * GSTR + s]);
            const __nv_bfloat16* pb = Wsrc + (size_t)(n0 + r) * K + k0 + s;
            CP_ASYNC16(db, pb, 16);
        }
    };

    stage(0, 0);
    CP_COMMIT();

    for (int c = 0; c < NC; c++) {
        if (c + 1 < NC) stage(c + 1, (c + 1) & 1);
        CP_COMMIT();
        CP_WAIT1();
        __syncthreads();

        const int buf = c & 1;
        const __nv_bfloat16* Ab = sA[buf];
        const __nv_bfloat16* Bb = sB[buf];
#pragma unroll
        for (int ks = 0; ks < 2; ks++) {
            const int kb = ks * 16;
            uint32_t af[4][4];
#pragma unroll
            for (int mt = 0; mt < 4; mt++) {
                int r = wm * 64 + mt * 16 + gr;
                af[mt][0] = *reinterpret_cast<const uint32_t*>(&Ab[(r)     * GSTR + kb + gc * 2]);
                af[mt][1] = *reinterpret_cast<const uint32_t*>(&Ab[(r + 8) * GSTR + kb + gc * 2]);
                af[mt][2] = *reinterpret_cast<const uint32_t*>(&Ab[(r)     * GSTR + kb + gc * 2 + 8]);
                af[mt][3] = *reinterpret_cast<const uint32_t*>(&Ab[(r + 8) * GSTR + kb + gc * 2 + 8]);
            }
#pragma unroll
            for (int nt = 0; nt < 4; nt++) {
                int n = wn * 32 + nt * 8 + gr;
                uint32_t b0 = *reinterpret_cast<const uint32_t*>(&Bb[n * GSTR + kb + gc * 2]);
                uint32_t b1 = *reinterpret_cast<const uint32_t*>(&Bb[n * GSTR + kb + gc * 2 + 8]);
#pragma unroll
                for (int mt = 0; mt < 4; mt++)
                    mma16816(acc[mt][nt][0], acc[mt][nt][1], acc[mt][nt][2], acc[mt][nt][3],
                             af[mt][0], af[mt][1], af[mt][2], af[mt][3], b0, b1);
            }
        }
        __syncthreads();
    }

    // epilogue
#pragma unroll
    for (int mt = 0; mt < 4; mt++) {
        int r0 = m0 + wm * 64 + mt * 16 + gr;
        int r1 = r0 + 8;
#pragma unroll
        for (int nt = 0; nt < 4; nt++) {
            int n = n0 + wn * 32 + nt * 8 + gc * 2;
            if (!FUSE_OUT) {
                if (r0 < M)
                    *reinterpret_cast<float2*>(&C[(size_t)r0 * Ntot + n]) =
                        make_float2(acc[mt][nt][0], acc[mt][nt][1]);
                if (r1 < M)
                    *reinterpret_cast<float2*>(&C[(size_t)r1 * Ntot + n]) =
                        make_float2(acc[mt][nt][2], acc[mt][nt][3]);
            } else {
#pragma unroll
                for (int half = 0; half < 2; half++) {
                    int m = half ? r1 : r0;
                    if (m >= M) continue;
                    int b = m / LSEQ, l = m % LSEQ;
                    if (l == 0) continue;
                    int lp = l - 1;
                    int H2 = lp / 48, W2 = lp % 48;
                    int sub = (H2 & 1) * 2 + (W2 & 1);
                    int base = ((b * 1024 + sub) * 24 + (H2 >> 1)) * 24 + (W2 >> 1);
                    float v0 = half ? acc[mt][nt][2] : acc[mt][nt][0];
                    float v1 = half ? acc[mt][nt][3] : acc[mt][nt][1];
                    C[base + (n    ) * 4 * 576] = v0;
                    C[base + (n + 1) * 4 * 576] = v1;
                }
            }
        }
    }
}

// ---------------- 3) causal depthwise conv (k=4) + bias + silu ----------------
__global__ void conv_kernel(const float* __restrict__ conv_w,
                            const float* __restrict__ conv_b) {
    int idx = blockIdx.x * blockDim.x + threadIdx.x;
    if (idx >= MROWS * DI) return;
    int d = idx % DI;
    int l = (idx / DI) % LSEQ;
    int b = idx / (DI * LSEQ);
    float acc = conv_b[d];
#pragma unroll
    for (int k = 0; k < 4; k++) {
        int ls = l - 3 + k;
        if (ls >= 0)
            acc = fmaf(g_xz[((size_t)(b * LSEQ + ls)) * (2 * DI) + d], conv_w[d * 4 + k], acc);
    }
    g_u[(size_t)(b * LSEQ + l) * DI + d] = siluf(acc);
}

// ---------------- 4) fused x_proj (N=48) + dt projection + softplus ----------------
// 32-row M-tiles -> 290 CTAs (~2/SM) for better issue coverage.
__global__ __launch_bounds__(256)
void xproj_dt_kernel(const float* __restrict__ xw,
                     const float* __restrict__ Wdt,
                     const float* __restrict__ bdt) {
    __shared__ union {
        struct { float As[32][32]; float Ws[32][48]; } p1;   // 4KB + 6KB
        struct { float xs[32][48]; float wdt[16][512]; } p2; // 6KB + 32KB
    } sm;
    const int tid = threadIdx.x;
    const int m0 = blockIdx.x * 32;
    const int tr = tid >> 4;   // 0..15 -> 2-row group
    const int tc = tid & 15;   // 0..15 -> 3-col group

    float acc[2][3];
#pragma unroll
    for (int i = 0; i < 2; i++)
#pragma unroll
        for (int j = 0; j < 3; j++) acc[i][j] = 0.0f;

    for (int step = 0; step < 16; step++) {
        int k0 = step * 32;
        // load A tile (32 rows x 32 k) transposed -> As[k][m]; 1 float4/thread
        {
            int row = tid >> 3;           // 0..31
            int c4 = (tid & 7) * 4;       // k offset
            float4 v = make_float4(0.f, 0.f, 0.f, 0.f);
            if (m0 + row < MROWS)
                v = *reinterpret_cast<const float4*>(&g_u[(size_t)(m0 + row) * DI + k0 + c4]);
            sm.p1.As[c4+0][row] = v.x; sm.p1.As[c4+1][row] = v.y;
            sm.p1.As[c4+2][row] = v.z; sm.p1.As[c4+3][row] = v.w;
        }
        // load W tile (48 x 32) transposed -> Ws[k][n]
        for (int t = tid; t < 384; t += 256) {
            int n = t >> 3;
            int c4 = (t & 7) * 4;
            float4 v = *reinterpret_cast<const float4*>(&xw[(size_t)n * DI + k0 + c4]);
            sm.p1.Ws[c4+0][n] = v.x; sm.p1.Ws[c4+1][n] = v.y;
            sm.p1.Ws[c4+2][n] = v.z; sm.p1.Ws[c4+3][n] = v.w;
        }
        __syncthreads();
#pragma unroll
        for (int k = 0; k < 32; k++) {
            float a0 = sm.p1.As[k][tr * 2 + 0];
            float a1 = sm.p1.As[k][tr * 2 + 1];
            float b0 = sm.p1.Ws[k][tc*3+0];
            float b1 = sm.p1.Ws[k][tc*3+1];
            float b2 = sm.p1.Ws[k][tc*3+2];
            acc[0][0] = fmaf(a0, b0, acc[0][0]);
            acc[0][1] = fmaf(a0, b1, acc[0][1]);
            acc[0][2] = fmaf(a0, b2, acc[0][2]);
            acc[1][0] = fmaf(a1, b0, acc[1][0]);
            acc[1][1] = fmaf(a1, b1, acc[1][1]);
            acc[1][2] = fmaf(a1, b2, acc[1][2]);
        }
        __syncthreads();
    }

    // write x_dbl to global + smem
#pragma unroll
    for (int i = 0; i < 2; i++) {
        int m = m0 + tr * 2 + i;
#pragma unroll
        for (int j = 0; j < 3; j++) {
            int n = tc * 3 + j;
            sm.p2.xs[tr * 2 + i][n] = acc[i][j];
            if (m < MROWS) g_xdbl[(size_t)m * NDBL + n] = acc[i][j];
        }
    }
    for (int t = tid; t < DI * DTR; t += 256) {
        int d = t >> 4, k = t & 15;
        sm.p2.wdt[k][d] = Wdt[t];
    }
    __syncthreads();

    // dt phase: each thread owns 2 d-channels across 32 rows
    const int d0 = tid * 2;
    float wr0[16], wr1[16];
#pragma unroll
    for (int k = 0; k < 16; k++) { wr0[k] = sm.p2.wdt[k][d0]; wr1[k] = sm.p2.wdt[k][d0+1]; }
    const float b0 = bdt[d0], b1 = bdt[d0+1];
    for (int row = 0; row < 32; row++) {
        int m = m0 + row;
        if (m >= MROWS) break;
        float a0 = b0, a1 = b1;
#pragma unroll
        for (int k = 0; k < 16; k++) {
            float xv = sm.p2.xs[row][k];
            a0 = fmaf(xv, wr0[k], a0);
            a1 = fmaf(xv, wr1[k], a1);
        }
        float2 o = make_float2(softplusf(a0), softplusf(a1));
        *reinterpret_cast<float2*>(&g_dt[(size_t)m * DI + d0]) = o;
    }
}

// ---------------- power-chain dA helper ----------------
__device__ __forceinline__ void da_powers(float e1, float dA[DS]) {
    float e2 = e1 * e1;
    float e4 = e2 * e2;
    float e8 = e4 * e4;
    dA[0]=e1;        dA[1]=e2;        dA[2]=e2*e1;     dA[3]=e4;
    dA[4]=e4*e1;     dA[5]=e4*e2;     dA[6]=e4*e2*e1;  dA[7]=e8;
    dA[8]=e8*e1;     dA[9]=e8*e2;     dA[10]=e8*e2*e1; dA[11]=e8*e4;
    dA[12]=e8*e4*e1; dA[13]=e8*e4*e2; dA[14]=e8*e4*e2*e1; dA[15]=e8*e8;
}

// ---------------- 5) scan pass 1 ----------------
__global__ void scan_pass1_kernel(const float* __restrict__ A_log) {
    int d = blockIdx.x * 128 + threadIdx.x;
    int c = blockIdx.y;
    int b = blockIdx.z;
    float Aa[DS], h[DS], P[DS];
    bool chain = true;
#pragma unroll
    for (int n = 0; n < DS; n++) {
        Aa[n] = -__expf(A_log[d * DS + n]);
        h[n] = 0.0f; P[n] = 1.0f;
    }
    float a1 = Aa[0];
#pragma unroll
    for (int n = 0; n < DS; n++)
        chain = chain && (fabsf(Aa[n] - a1 * (n + 1)) < 1e-3f * (n + 1));

    int l0 = c * CHUNK;
    int l1 = min(LSEQ, l0 + CHUNK);
    for (int l = l0; l < l1; l++) {
        size_t row = (size_t)b * LSEQ + l;
        float dtv = g_dt[row * DI + d];
        float uv  = g_u [row * DI + d];
        float du  = dtv * uv;
        const float4* Bp = reinterpret_cast<const float4*>(&g_xdbl[row * NDBL + DTR]);
        float4 t0 = Bp[0], t1 = Bp[1], t2 = Bp[2], t3 = Bp[3];
        float Bv[DS] = {t0.x, t0.y, t0.z, t0.w, t1.x, t1.y, t1.z, t1.w,
                        t2.x, t2.y, t2.z, t2.w, t3.x, t3.y, t3.z, t3.w};
        float dA[DS];
        if (chain) {
            da_powers(__expf(dtv * a1), dA);
        } else {
#pragma unroll
            for (int n = 0; n < DS; n++) dA[n] = __expf(dtv * Aa[n]);
        }
#pragma unroll
        for (int n = 0; n < DS; n++) {
            P[n] *= dA[n];
            h[n] = fmaf(dA[n], h[n], du * Bv[n]);
        }
    }
    size_t base = (((size_t)b * DI + d) * NCHUNK + c) * DS;
#pragma unroll
    for (int n = 0; n < DS; n++) { g_P[base + n] = P[n]; g_hf[base + n] = h[n]; }
}

// ---------------- 6) sequential combine ----------------
__global__ void scan_combine_kernel() {
    int idx = blockIdx.x * blockDim.x + threadIdx.x;
    if (idx >= BATCH * DI * DS) return;
    int n = idx % DS;
    int d = (idx / DS) % DI;
    int b = idx / (DS * DI);
    float h = 0.0f;
    for (int c = 0; c < NCHUNK; c++) {
        size_t base = (((size_t)b * DI + d) * NCHUNK + c) * DS + n;
        g_hin[base] = h;
        h = fmaf(g_P[base], h, g_hf[base]);
    }
}

// ---------------- 7) scan pass 2 + gating, writes bf16 hi/lo y ----------------
__global__ void scan_pass2_kernel(const float* __restrict__ A_log,
                                  const float* __restrict__ Dp) {
    int d = blockIdx.x * 128 + threadIdx.x;
    int c = blockIdx.y;
    int b = blockIdx.z;
    float Aa[DS], h[DS];
    size_t hbase = (((size_t)b * DI + d) * NCHUNK + c) * DS;
    bool chain = true;
#pragma unroll
    for (int n = 0; n < DS; n++) {
        Aa[n] = -__expf(A_log[d * DS + n]);
        h[n] = g_hin[hbase + n];
    }
    float a1 = Aa[0];
#pragma unroll
    for (int n = 0; n < DS; n++)
        chain = chain && (fabsf(Aa[n] - a1 * (n + 1)) < 1e-3f * (n + 1));

    float Dd = Dp[d];
    int l0 = c * CHUNK;
    int l1 = min(LSEQ, l0 + CHUNK);
    for (int l = l0; l < l1; l++) {
        size_t row = (size_t)b * LSEQ + l;
        float dtv = g_dt[row * DI + d];
        float uv  = g_u [row * DI + d];
        float du  = dtv * uv;
        const float4* BCp = reinterpret_cast<const float4*>(&g_xdbl[row * NDBL + DTR]);
        float4 t0 = BCp[0], t1 = BCp[1], t2 = BCp[2], t3 = BCp[3];
        float4 t4 = BCp[4], t5 = BCp[5], t6 = BCp[6], t7 = BCp[7];
        float Bv[DS] = {t0.x, t0.y, t0.z, t0.w, t1.x, t1.y, t1.z, t1.w,
                        t2.x, t2.y, t2.z, t2.w, t3.x, t3.y, t3.z, t3.w};
        float Cv[DS] = {t4.x, t4.y, t4.z, t4.w, t5.x, t5.y, t5.z, t5.w,
                        t6.x, t6.y, t6.z, t6.w, t7.x, t7.y, t7.z, t7.w};
        float dA[DS];
        if (chain) {
            da_powers(__expf(dtv * a1), dA);
        } else {
#pragma unroll
            for (int n = 0; n < DS; n++) dA[n] = __expf(dtv * Aa[n]);
        }
        float y = 0.0f;
#pragma unroll
        for (int n = 0; n < DS; n++) {
            h[n] = fmaf(dA[n], h[n], du * Bv[n]);
            y = fmaf(h[n], Cv[n], y);
        }
        float z = g_xz[row * (2 * DI) + DI + d];
        float yv = (y + uv * Dd) * siluf(z);
        __nv_bfloat16 hh, ll;
        split_bf16(yv, hh, ll);
        g_yh[row * DI + d] = hh;
        g_yl[row * DI + d] = ll;
    }
}

// ---------------- launch ----------------
extern "C" void kernel_launch(void* const* d_in, const int* in_sizes, int n_in,
                              void* d_out, int out_size) {
    const float* x          = (const float*)d_in[0];
    const float* gtok       = (const float*)d_in[1];
    const float* in_proj_w  = (const float*)d_in[2];
    const float* conv_w     = (const float*)d_in[3];
    const float* conv_b     = (const float*)d_in[4];
    const float* x_proj_w   = (const float*)d_in[5];
    const float* dt_proj_w  = (const float*)d_in[6];
    const float* dt_proj_b  = (const float*)d_in[7];
    const float* A_log      = (const float*)d_in[8];
    const float* Dp         = (const float*)d_in[9];
    const float* out_proj_w = (const float*)d_in[10];
    float* out = (float*)d_out;

    float *p_xz;
    __nv_bfloat16 *p_seqh, *p_seql, *p_yh, *p_yl, *p_wih, *p_wil, *p_woh, *p_wol;
    cudaGetSymbolAddress((void**)&p_xz,   g_xz);
    cudaGetSymbolAddress((void**)&p_seqh, g_seqh);
    cudaGetSymbolAddress((void**)&p_seql, g_seql);
    cudaGetSymbolAddress((void**)&p_yh,   g_yh);
    cudaGetSymbolAddress((void**)&p_yl,   g_yl);
    cudaGetSymbolAddress((void**)&p_wih,  g_wih);
    cudaGetSymbolAddress((void**)&p_wil,  g_wil);
    cudaGetSymbolAddress((void**)&p_woh,  g_woh);
    cudaGetSymbolAddress((void**)&p_wol,  g_wol);

    // 1. seq (bf16 hi/lo) + weight splits
    build_seq_kernel<<<(MROWS * DM + 255) / 256, 256>>>(x, gtok);
    split_kernel<<<(2 * DI * DM + 255) / 256, 256>>>(in_proj_w, p_wih, p_wil, 2 * DI * DM);
    split_kernel<<<(DM * DI + 255) / 256, 256>>>(out_proj_w, p_woh, p_wol, DM * DI);

    // 2. xz = seq @ in_proj_w^T  (mma.sync bf16x3, M=9220, N=1024, K=256)
    {
        dim3 grid((MROWS + 127) / 128, (2 * DI) / 128);
        gemm_mma_kernel<false><<<grid, 256>>>(p_seqh, p_seql, p_wih, p_wil,
                                              p_xz, MROWS, 2 * DI, DM);
    }

    // 3. u = silu(causal_conv(xz[:, :512]) + b)
    conv_kernel<<<(MROWS * DI + 255) / 256, 256>>>(conv_w, conv_b);

    // 4+5. x_dbl + dt (fused), 32-row tiles
    xproj_dt_kernel<<<(MROWS + 31) / 32, 256>>>(x_proj_w, dt_proj_w, dt_proj_b);

    // 6-8. chunked selective scan + gating
    {
        dim3 grid(DI / 128, NCHUNK, BATCH);
        scan_pass1_kernel<<<grid, 128>>>(A_log);
        scan_combine_kernel<<<(BATCH * DI * DS + 255) / 256, 256>>>();
        scan_pass2_kernel<<<grid, 128>>>(A_log, Dp);
    }

    // 9. out = y @ out_proj_w^T (mma.sync bf16x3, fused pixel_unshuffle, N=256, K=512)
    {
        dim3 grid((MROWS + 127) / 128, DM / 128);
        gemm_mma_kernel<true><<<grid, 256>>>(p_yh, p_yl, p_woh, p_wol,
                                             out, MROWS, DM, DI);
    }
}

// round 14
// speedup vs baseline: 1.5809x; 1.5809x over previous
#include <cuda_runtime.h>
#include <cuda_bf16.h>
#include <math.h>
#include <cstdint>

// ---------------- problem constants ----------------
#define BATCH   4
#define LSEQ    2305          // 1 global token + 48*48
#define DM      256           // D_MODEL
#define DI      512           // D_INNER
#define DS      16            // D_STATE
#define DTR     16            // DT_RANK
#define NDBL    48            // DTR + 2*D_STATE
#define MROWS   (BATCH*LSEQ)  // 9220
#define CHUNK   32
#define NCHUNK  73            // ceil(2305/32)

// ---------------- scratch (device globals; no allocation allowed) ----------------
__device__ __nv_bfloat16 g_seqh[MROWS*DM];
__device__ __nv_bfloat16 g_seql[MROWS*DM];
__device__ float g_xz  [MROWS*2*DI];
__device__ float g_u   [MROWS*DI];
__device__ float g_xdbl[MROWS*NDBL];
__device__ float g_dt  [MROWS*DI];
__device__ __nv_bfloat16 g_yh[MROWS*DI];
__device__ __nv_bfloat16 g_yl[MROWS*DI];
__device__ float g_P   [BATCH*DI*NCHUNK*DS];
__device__ float g_hf  [BATCH*DI*NCHUNK*DS];
__device__ float g_hin [BATCH*DI*NCHUNK*DS];
// split weights
__device__ __nv_bfloat16 g_wih[2*DI*DM], g_wil[2*DI*DM];   // in_proj 1024x256
__device__ __nv_bfloat16 g_woh[DM*DI],   g_wol[DM*DI];     // out_proj 256x512

// ---------------- math helpers ----------------
__device__ __forceinline__ float siluf(float x) { return x / (1.0f + __expf(-x)); }
__device__ __forceinline__ float softplusf(float x) {
    return fmaxf(x, 0.0f) + log1pf(__expf(-fabsf(x)));
}
__device__ __forceinline__ void split_bf16(float v, __nv_bfloat16& h, __nv_bfloat16& l) {
    h = __float2bfloat16(v);
    l = __float2bfloat16(v - __bfloat162float(h));
}
__device__ __forceinline__ uint32_t smem_u32(const void* p) {
    uint32_t a;
    asm("{ .reg .u64 t; cvta.to.shared.u64 t, %1; cvt.u32.u64 %0, t; }" : "=r"(a) : "l"(p));
    return a;
}
#define CP_ASYNC16(dst, src, nbytes) \
    asm volatile("cp.async.cg.shared.global [%0], [%1], 16, %2;" \
                 :: "r"(dst), "l"(src), "r"(nbytes))
#define CP_COMMIT()  asm volatile("cp.async.commit_group;" ::: "memory")
#define CP_WAIT1()   asm volatile("cp.async.wait_group 1;" ::: "memory")

__device__ __forceinline__ void mma16816(float& c0, float& c1, float& c2, float& c3,
                                         uint32_t a0, uint32_t a1, uint32_t a2, uint32_t a3,
                                         uint32_t b0, uint32_t b1) {
    asm volatile("mma.sync.aligned.m16n8k16.row.col.f32.bf16.bf16.f32 "
                 "{%0,%1,%2,%3}, {%4,%5,%6,%7}, {%8,%9}, {%0,%1,%2,%3};"
                 : "+f"(c0), "+f"(c1), "+f"(c2), "+f"(c3)
                 : "r"(a0), "r"(a1), "r"(a2), "r"(a3), "r"(b0), "r"(b1));
}
__device__ __forceinline__ void ldsm_x4(uint32_t& r0, uint32_t& r1, uint32_t& r2, uint32_t& r3,
                                        uint32_t addr) {
    asm volatile("ldmatrix.sync.aligned.m8n8.x4.shared.b16 {%0,%1,%2,%3}, [%4];"
                 : "=r"(r0), "=r"(r1), "=r"(r2), "=r"(r3) : "r"(addr));
}
__device__ __forceinline__ void ldsm_x2(uint32_t& r0, uint32_t& r1, uint32_t addr) {
    asm volatile("ldmatrix.sync.aligned.m8n8.x2.shared.b16 {%0,%1}, [%2];"
                 : "=r"(r0), "=r"(r1) : "r"(addr));
}

// ---------------- 1) build seq (writes bf16 hi/lo) ----------------
__global__ void build_seq_kernel(const float* __restrict__ x,
                                 const float* __restrict__ gtok) {
    int idx = blockIdx.x * blockDim.x + threadIdx.x;
    if (idx >= MROWS * DM) return;
    int c = idx % DM;
    int l = (idx / DM) % LSEQ;
    int b = idx / (DM * LSEQ);
    float v;
    if (l == 0) {
        v = gtok[c];
    } else {
        int lp = l - 1;
        int H2 = lp / 48, W2 = lp % 48;
        int ch = c * 4 + (H2 & 1) * 2 + (W2 & 1);
        v = x[((b * 1024 + ch) * 24 + (H2 >> 1)) * 24 + (W2 >> 1)];
    }
    __nv_bfloat16 h, lo;
    split_bf16(v, h, lo);
    g_seqh[idx] = h; g_seql[idx] = lo;
}

// ---------------- weight hi/lo split ----------------
__global__ void split_kernel(const float* __restrict__ s,
                             __nv_bfloat16* __restrict__ h,
                             __nv_bfloat16* __restrict__ l, int n) {
    int i = blockIdx.x * blockDim.x + threadIdx.x;
    if (i >= n) return;
    __nv_bfloat16 hv, lv;
    split_bf16(s[i], hv, lv);
    h[i] = hv; l[i] = lv;
}

// ---------------- 2) bf16 mma.sync GEMM with ldmatrix ----------------
// C[M,Ntot] = A[M,K] @ W[Ntot,K]^T, fp32 emulation via 3 bf16 segments.
// CTA tile 128x128, 8 warps (2m x 4n), warp tile 64x32, BK=32, cp.async
// double buffering. GSTR=40 bf16 (80B rows): ldmatrix phase-conflict-free.
#define GSTR 40

template<bool FUSE_OUT>
__global__ __launch_bounds__(256, 2)
void gemm_mma_kernel(const __nv_bfloat16* __restrict__ Ah,
                     const __nv_bfloat16* __restrict__ Al,
                     const __nv_bfloat16* __restrict__ Wh,
                     const __nv_bfloat16* __restrict__ Wl,
                     float* __restrict__ C, int M, int Ntot, int K) {
    __shared__ __align__(16) union SmemU {
        struct { __nv_bfloat16 A[2][128 * GSTR]; __nv_bfloat16 B[2][128 * GSTR]; } p;
        float xf[128 * 65];   // FUSE_OUT staging (33280B <= 40960B)
    } su;

    const int tid = threadIdx.x;
    const int wid = tid >> 5;
    const int lane = tid & 31;
    const int gr = lane >> 2;     // 0..7
    const int gc = lane & 3;      // 0..3
    const int wm = wid >> 2;      // 0..1
    const int wn = wid & 3;       // 0..3
    const int m0 = blockIdx.x * 128;
    const int n0 = blockIdx.y * 128;

    // ldmatrix lane->address components
    const int a_row = lane & 15;          // row offset within 16
    const int a_khi = (lane >> 4) * 8;    // 0 or 8
    const int b_row = lane & 7;
    const int b_khi = (lane & 8) ? 8 : 0; // lanes 0-15 meaningful; 16-31 replicate

    const int kseg = K >> 5;
    const int NC = 3 * kseg;

    float acc[4][4][4];
#pragma unroll
    for (int i = 0; i < 4; i++)
#pragma unroll
        for (int j = 0; j < 4; j++)
#pragma unroll
            for (int q = 0; q < 4; q++) acc[i][j][q] = 0.0f;

    auto stage = [&](int c, int buf) {
        const int seg = c / kseg;
        const int k0 = (c - seg * kseg) * 32;
        const __nv_bfloat16* Asrc = (seg == 1) ? Al : Ah;
        const __nv_bfloat16* Wsrc = (seg == 2) ? Wl : Wh;
#pragma unroll
        for (int q = 0; q < 2; q++) {
            int i = tid * 2 + q;
            int r = i >> 2;
            int s = (i & 3) * 8;
            uint32_t da = smem_u32(&su.p.A[buf][r * GSTR + s]);
            const __nv_bfloat16* pa = Asrc + (size_t)(m0 + r) * K + k0 + s;
            CP_ASYNC16(da, pa, (m0 + r < M) ? 16 : 0);
            uint32_t db = smem_u32(&su.p.B[buf][r * GSTR + s]);
            const __nv_bfloat16* pb = Wsrc + (size_t)(n0 + r) * K + k0 + s;
            CP_ASYNC16(db, pb, 16);
        }
    };

    stage(0, 0);
    CP_COMMIT();

    for (int c = 0; c < NC; c++) {
        if (c + 1 < NC) stage(c + 1, (c + 1) & 1);
        CP_COMMIT();
        CP_WAIT1();
        __syncthreads();

        const int buf = c & 1;
        const __nv_bfloat16* Ab = su.p.A[buf];
        const __nv_bfloat16* Bb = su.p.B[buf];
#pragma unroll
        for (int ks = 0; ks < 2; ks++) {
            const int kb = ks * 16;
            uint32_t af[4][4];
#pragma unroll
            for (int mt = 0; mt < 4; mt++) {
                uint32_t addr = smem_u32(&Ab[(wm * 64 + mt * 16 + a_row) * GSTR + kb + a_khi]);
                ldsm_x4(af[mt][0], af[mt][1], af[mt][2], af[mt][3], addr);
            }
#pragma unroll
            for (int nt = 0; nt < 4; nt++) {
                uint32_t baddr = smem_u32(&Bb[(wn * 32 + nt * 8 + b_row) * GSTR + kb + b_khi]);
                uint32_t b0, b1;
                ldsm_x2(b0, b1, baddr);
#pragma unroll
                for (int mt = 0; mt < 4; mt++)
                    mma16816(acc[mt][nt][0], acc[mt][nt][1], acc[mt][nt][2], acc[mt][nt][3],
                             af[mt][0], af[mt][1], af[mt][2], af[mt][3], b0, b1);
            }
        }
        __syncthreads();
    }

    if (!FUSE_OUT) {
#pragma unroll
        for (int mt = 0; mt < 4; mt++) {
            int r0 = m0 + wm * 64 + mt * 16 + gr;
            int r1 = r0 + 8;
#pragma unroll
            for (int nt = 0; nt < 4; nt++) {
                int n = n0 + wn * 32 + nt * 8 + gc * 2;
                if (r0 < M)
                    *reinterpret_cast<float2*>(&C[(size_t)r0 * Ntot + n]) =
                        make_float2(acc[mt][nt][0], acc[mt][nt][1]);
                if (r1 < M)
                    *reinterpret_cast<float2*>(&C[(size_t)r1 * Ntot + n]) =
                        make_float2(acc[mt][nt][2], acc[mt][nt][3]);
            }
        }
    } else {
        // coalesced pixel_unshuffle scatter via smem staging (two 64-col halves)
#pragma unroll
        for (int half = 0; half < 2; half++) {
            __syncthreads();
            if ((wn >> 1) == half) {
                int csub = wn & 1;
#pragma unroll
                for (int mt = 0; mt < 4; mt++) {
                    int rl0 = wm * 64 + mt * 16 + gr;
#pragma unroll
                    for (int nt = 0; nt < 4; nt++) {
                        int cl = csub * 32 + nt * 8 + gc * 2;
                        su.xf[rl0 * 65 + cl]       = acc[mt][nt][0];
                        su.xf[rl0 * 65 + cl + 1]   = acc[mt][nt][1];
                        su.xf[(rl0+8) * 65 + cl]   = acc[mt][nt][2];
                        su.xf[(rl0+8) * 65 + cl+1] = acc[mt][nt][3];
                    }
                }
            }
            __syncthreads();
#pragma unroll 4
            for (int it = 0; it < 32; it++) {
                int idx = it * 256 + tid;       // 0..8191 = 128 rows x 64 cols
                int ml = idx & 127;
                int cl = idx >> 7;              // 0..63
                int m = m0 + ml;
                if (m < M) {
                    int b = m / LSEQ, l = m % LSEQ;
                    if (l > 0) {
                        int lp = l - 1;
                        int H2 = lp / 48, W2 = lp % 48;
                        int sub = (H2 & 1) * 2 + (W2 & 1);
                        int n = n0 + half * 64 + cl;
                        C[((b * 1024 + n * 4 + sub) * 24 + (H2 >> 1)) * 24 + (W2 >> 1)] =
                            su.xf[ml * 65 + cl];
                    }
                }
            }
        }
    }
}

// ---------------- 3) causal depthwise conv (k=4) + bias + silu ----------------
__global__ void conv_kernel(const float* __restrict__ conv_w,
                            const float* __restrict__ conv_b) {
    int idx = blockIdx.x * blockDim.x + threadIdx.x;
    if (idx >= MROWS * DI) return;
    int d = idx % DI;
    int l = (idx / DI) % LSEQ;
    int b = idx / (DI * LSEQ);
    float acc = conv_b[d];
#pragma unroll
    for (int k = 0; k < 4; k++) {
        int ls = l - 3 + k;
        if (ls >= 0)
            acc = fmaf(g_xz[((size_t)(b * LSEQ + ls)) * (2 * DI) + d], conv_w[d * 4 + k], acc);
    }
    g_u[(size_t)(b * LSEQ + l) * DI + d] = siluf(acc);
}

// ---------------- 4) fused x_proj (N=48) + dt projection + softplus ----------------
__global__ __launch_bounds__(256)
void xproj_dt_kernel(const float* __restrict__ xw,
                     const float* __restrict__ Wdt,
                     const float* __restrict__ bdt) {
    __shared__ union {
        struct { float As[32][32]; float Ws[32][48]; } p1;
        struct { float xs[32][48]; float wdt[16][512]; } p2;
    } sm;
    const int tid = threadIdx.x;
    const int m0 = blockIdx.x * 32;
    const int tr = tid >> 4;
    const int tc = tid & 15;

    float acc[2][3];
#pragma unroll
    for (int i = 0; i < 2; i++)
#pragma unroll
        for (int j = 0; j < 3; j++) acc[i][j] = 0.0f;

    for (int step = 0; step < 16; step++) {
        int k0 = step * 32;
        {
            int row = tid >> 3;
            int c4 = (tid & 7) * 4;
            float4 v = make_float4(0.f, 0.f, 0.f, 0.f);
            if (m0 + row < MROWS)
                v = *reinterpret_cast<const float4*>(&g_u[(size_t)(m0 + row) * DI + k0 + c4]);
            sm.p1.As[c4+0][row] = v.x; sm.p1.As[c4+1][row] = v.y;
            sm.p1.As[c4+2][row] = v.z; sm.p1.As[c4+3][row] = v.w;
        }
        for (int t = tid; t < 384; t += 256) {
            int n = t >> 3;
            int c4 = (t & 7) * 4;
            float4 v = *reinterpret_cast<const float4*>(&xw[(size_t)n * DI + k0 + c4]);
            sm.p1.Ws[c4+0][n] = v.x; sm.p1.Ws[c4+1][n] = v.y;
            sm.p1.Ws[c4+2][n] = v.z; sm.p1.Ws[c4+3][n] = v.w;
        }
        __syncthreads();
#pragma unroll
        for (int k = 0; k < 32; k++) {
            float a0 = sm.p1.As[k][tr * 2 + 0];
            float a1 = sm.p1.As[k][tr * 2 + 1];
            float b0 = sm.p1.Ws[k][tc*3+0];
            float b1 = sm.p1.Ws[k][tc*3+1];
            float b2 = sm.p1.Ws[k][tc*3+2];
            acc[0][0] = fmaf(a0, b0, acc[0][0]);
            acc[0][1] = fmaf(a0, b1, acc[0][1]);
            acc[0][2] = fmaf(a0, b2, acc[0][2]);
            acc[1][0] = fmaf(a1, b0, acc[1][0]);
            acc[1][1] = fmaf(a1, b1, acc[1][1]);
            acc[1][2] = fmaf(a1, b2, acc[1][2]);
        }
        __syncthreads();
    }

#pragma unroll
    for (int i = 0; i < 2; i++) {
        int m = m0 + tr * 2 + i;
#pragma unroll
        for (int j = 0; j < 3; j++) {
            int n = tc * 3 + j;
            sm.p2.xs[tr * 2 + i][n] = acc[i][j];
            if (m < MROWS) g_xdbl[(size_t)m * NDBL + n] = acc[i][j];
        }
    }
    for (int t = tid; t < DI * DTR; t += 256) {
        int d = t >> 4, k = t & 15;
        sm.p2.wdt[k][d] = Wdt[t];
    }
    __syncthreads();

    const int d0 = tid * 2;
    float wr0[16], wr1[16];
#pragma unroll
    for (int k = 0; k < 16; k++) { wr0[k] = sm.p2.wdt[k][d0]; wr1[k] = sm.p2.wdt[k][d0+1]; }
    const float b0 = bdt[d0], b1 = bdt[d0+1];
    for (int row = 0; row < 32; row++) {
        int m = m0 + row;
        if (m >= MROWS) break;
        float a0 = b0, a1 = b1;
#pragma unroll
        for (int k = 0; k < 16; k++) {
            float xv = sm.p2.xs[row][k];
            a0 = fmaf(xv, wr0[k], a0);
            a1 = fmaf(xv, wr1[k], a1);
        }
        float2 o = make_float2(softplusf(a0), softplusf(a1));
        *reinterpret_cast<float2*>(&g_dt[(size_t)m * DI + d0]) = o;
    }
}

// ---------------- power-chain dA helper ----------------
__device__ __forceinline__ void da_powers(float e1, float dA[DS]) {
    float e2 = e1 * e1;
    float e4 = e2 * e2;
    float e8 = e4 * e4;
    dA[0]=e1;        dA[1]=e2;        dA[2]=e2*e1;     dA[3]=e4;
    dA[4]=e4*e1;     dA[5]=e4*e2;     dA[6]=e4*e2*e1;  dA[7]=e8;
    dA[8]=e8*e1;     dA[9]=e8*e2;     dA[10]=e8*e2*e1; dA[11]=e8*e4;
    dA[12]=e8*e4*e1; dA[13]=e8*e4*e2; dA[14]=e8*e4*e2*e1; dA[15]=e8*e8;
}

// ---------------- 5) scan pass 1 ----------------
__global__ void scan_pass1_kernel(const float* __restrict__ A_log) {
    int d = blockIdx.x * 128 + threadIdx.x;
    int c = blockIdx.y;
    int b = blockIdx.z;
    float Aa[DS], h[DS], P[DS];
    bool chain = true;
#pragma unroll
    for (int n = 0; n < DS; n++) {
        Aa[n] = -__expf(A_log[d * DS + n]);
        h[n] = 0.0f; P[n] = 1.0f;
    }
    float a1 = Aa[0];
#pragma unroll
    for (int n = 0; n < DS; n++)
        chain = chain && (fabsf(Aa[n] - a1 * (n + 1)) < 1e-3f * (n + 1));

    int l0 = c * CHUNK;
    int l1 = min(LSEQ, l0 + CHUNK);
    for (int l = l0; l < l1; l++) {
        size_t row = (size_t)b * LSEQ + l;
        float dtv = g_dt[row * DI + d];
        float uv  = g_u [row * DI + d];
        float du  = dtv * uv;
        const float4* Bp = reinterpret_cast<const float4*>(&g_xdbl[row * NDBL + DTR]);
        float4 t0 = Bp[0], t1 = Bp[1], t2 = Bp[2], t3 = Bp[3];
        float Bv[DS] = {t0.x, t0.y, t0.z, t0.w, t1.x, t1.y, t1.z, t1.w,
                        t2.x, t2.y, t2.z, t2.w, t3.x, t3.y, t3.z, t3.w};
        float dA[DS];
        if (chain) {
            da_powers(__expf(dtv * a1), dA);
        } else {
#pragma unroll
            for (int n = 0; n < DS; n++) dA[n] = __expf(dtv * Aa[n]);
        }
#pragma unroll
        for (int n = 0; n < DS; n++) {
            P[n] *= dA[n];
            h[n] = fmaf(dA[n], h[n], du * Bv[n]);
        }
    }
    size_t base = (((size_t)b * DI + d) * NCHUNK + c) * DS;
#pragma unroll
    for (int n = 0; n < DS; n++) { g_P[base + n] = P[n]; g_hf[base + n] = h[n]; }
}

// ---------------- 6) sequential combine ----------------
__global__ void scan_combine_kernel() {
    int idx = blockIdx.x * blockDim.x + threadIdx.x;
    if (idx >= BATCH * DI * DS) return;
    int n = idx % DS;
    int d = (idx / DS) % DI;
    int b = idx / (DS * DI);
    float h = 0.0f;
    for (int c = 0; c < NCHUNK; c++) {
        size_t base = (((size_t)b * DI + d) * NCHUNK + c) * DS + n;
        g_hin[base] = h;
        h = fmaf(g_P[base], h, g_hf[base]);
    }
}

// ---------------- 7) scan pass 2 + gating, writes bf16 hi/lo y ----------------
__global__ void scan_pass2_kernel(const float* __restrict__ A_log,
                                  const float* __restrict__ Dp) {
    int d = blockIdx.x * 128 + threadIdx.x;
    int c = blockIdx.y;
    int b = blockIdx.z;
    float Aa[DS], h[DS];
    size_t hbase = (((size_t)b * DI + d) * NCHUNK + c) * DS;
    bool chain = true;
#pragma unroll
    for (int n = 0; n < DS; n++) {
        Aa[n] = -__expf(A_log[d * DS + n]);
        h[n] = g_hin[hbase + n];
    }
    float a1 = Aa[0];
#pragma unroll
    for (int n = 0; n < DS; n++)
        chain = chain && (fabsf(Aa[n] - a1 * (n + 1)) < 1e-3f * (n + 1));

    float Dd = Dp[d];
    int l0 = c * CHUNK;
    int l1 = min(LSEQ, l0 + CHUNK);
    for (int l = l0; l < l1; l++) {
        size_t row = (size_t)b * LSEQ + l;
        float dtv = g_dt[row * DI + d];
        float uv  = g_u [row * DI + d];
        float du  = dtv * uv;
        const float4* BCp = reinterpret_cast<const float4*>(&g_xdbl[row * NDBL + DTR]);
        float4 t0 = BCp[0], t1 = BCp[1], t2 = BCp[2], t3 = BCp[3];
        float4 t4 = BCp[4], t5 = BCp[5], t6 = BCp[6], t7 = BCp[7];
        float Bv[DS] = {t0.x, t0.y, t0.z, t0.w, t1.x, t1.y, t1.z, t1.w,
                        t2.x, t2.y, t2.z, t2.w, t3.x, t3.y, t3.z, t3.w};
        float Cv[DS] = {t4.x, t4.y, t4.z, t4.w, t5.x, t5.y, t5.z, t5.w,
                        t6.x, t6.y, t6.z, t6.w, t7.x, t7.y, t7.z, t7.w};
        float dA[DS];
        if (chain) {
            da_powers(__expf(dtv * a1), dA);
        } else {
#pragma unroll
            for (int n = 0; n < DS; n++) dA[n] = __expf(dtv * Aa[n]);
        }
        float y = 0.0f;
#pragma unroll
        for (int n = 0; n < DS; n++) {
            h[n] = fmaf(dA[n], h[n], du * Bv[n]);
            y = fmaf(h[n], Cv[n], y);
        }
        float z = g_xz[row * (2 * DI) + DI + d];
        float yv = (y + uv * Dd) * siluf(z);
        __nv_bfloat16 hh, ll;
        split_bf16(yv, hh, ll);
        g_yh[row * DI + d] = hh;
        g_yl[row * DI + d] = ll;
    }
}

// ---------------- launch ----------------
extern "C" void kernel_launch(void* const* d_in, const int* in_sizes, int n_in,
                              void* d_out, int out_size) {
    const float* x          = (const float*)d_in[0];
    const float* gtok       = (const float*)d_in[1];
    const float* in_proj_w  = (const float*)d_in[2];
    const float* conv_w     = (const float*)d_in[3];
    const float* conv_b     = (const float*)d_in[4];
    const float* x_proj_w   = (const float*)d_in[5];
    const float* dt_proj_w  = (const float*)d_in[6];
    const float* dt_proj_b  = (const float*)d_in[7];
    const float* A_log      = (const float*)d_in[8];
    const float* Dp         = (const float*)d_in[9];
    const float* out_proj_w = (const float*)d_in[10];
    float* out = (float*)d_out;

    float *p_xz;
    __nv_bfloat16 *p_seqh, *p_seql, *p_yh, *p_yl, *p_wih, *p_wil, *p_woh, *p_wol;
    cudaGetSymbolAddress((void**)&p_xz,   g_xz);
    cudaGetSymbolAddress((void**)&p_seqh, g_seqh);
    cudaGetSymbolAddress((void**)&p_seql, g_seql);
    cudaGetSymbolAddress((void**)&p_yh,   g_yh);
    cudaGetSymbolAddress((void**)&p_yl,   g_yl);
    cudaGetSymbolAddress((void**)&p_wih,  g_wih);
    cudaGetSymbolAddress((void**)&p_wil,  g_wil);
    cudaGetSymbolAddress((void**)&p_woh,  g_woh);
    cudaGetSymbolAddress((void**)&p_wol,  g_wol);

    // 1. seq (bf16 hi/lo) + weight splits
    build_seq_kernel<<<(MROWS * DM + 255) / 256, 256>>>(x, gtok);
    split_kernel<<<(2 * DI * DM + 255) / 256, 256>>>(in_proj_w, p_wih, p_wil, 2 * DI * DM);
    split_kernel<<<(DM * DI + 255) / 256, 256>>>(out_proj_w, p_woh, p_wol, DM * DI);

    // 2. xz = seq @ in_proj_w^T  (ldmatrix + mma.sync bf16x3)
    {
        dim3 grid((MROWS + 127) / 128, (2 * DI) / 128);
        gemm_mma_kernel<false><<<grid, 256>>>(p_seqh, p_seql, p_wih, p_wil,
                                              p_xz, MROWS, 2 * DI, DM);
    }

    // 3. u = silu(causal_conv(xz[:, :512]) + b)
    conv_kernel<<<(MROWS * DI + 255) / 256, 256>>>(conv_w, conv_b);

    // 4+5. x_dbl + dt (fused)
    xproj_dt_kernel<<<(MROWS + 31) / 32, 256>>>(x_proj_w, dt_proj_w, dt_proj_b);

    // 6-8. chunked selective scan + gating (CHUNK=32 for 4x parallelism)
    {
        dim3 grid(DI / 128, NCHUNK, BATCH);
        scan_pass1_kernel<<<grid, 128>>>(A_log);
        scan_combine_kernel<<<(BATCH * DI * DS + 255) / 256, 256>>>();
        scan_pass2_kernel<<<grid, 128>>>(A_log, Dp);
    }

    // 9. out = y @ out_proj_w^T (fused coalesced pixel_unshuffle)
    {
        dim3 grid((MROWS + 127) / 128, DM / 128);
        gemm_mma_kernel<true><<<grid, 256>>>(p_yh, p_yl, p_woh, p_wol,
                                             out, MROWS, DM, DI);
    }
}

// round 15
// speedup vs baseline: 1.7084x; 1.0807x over previous
#include <cuda_runtime.h>
#include <cuda_bf16.h>
#include <math.h>
#include <cstdint>

// ---------------- problem constants ----------------
#define BATCH   4
#define LSEQ    2305          // 1 global token + 48*48
#define DM      256           // D_MODEL
#define DI      512           // D_INNER
#define DS      16            // D_STATE
#define DTR     16            // DT_RANK
#define NDBL    48            // DTR + 2*D_STATE
#define MROWS   (BATCH*LSEQ)  // 9220
#define CHUNK   32
#define NCHUNK  73            // ceil(2305/32)

// ---------------- scratch (device globals; no allocation allowed) ----------------
__device__ __nv_bfloat16 g_seqh[MROWS*DM];
__device__ __nv_bfloat16 g_seql[MROWS*DM];
__device__ float g_xz  [MROWS*2*DI];
__device__ float g_u   [MROWS*DI];
__device__ float g_xdbl[MROWS*NDBL];
__device__ float g_dt  [MROWS*DI];
__device__ __nv_bfloat16 g_yh[MROWS*DI];
__device__ __nv_bfloat16 g_yl[MROWS*DI];
__device__ float g_P   [BATCH*DI*NCHUNK*DS];
__device__ float g_hf  [BATCH*DI*NCHUNK*DS];
__device__ float g_hin [BATCH*DI*NCHUNK*DS];
// split weights
__device__ __nv_bfloat16 g_wih[2*DI*DM], g_wil[2*DI*DM];   // in_proj 1024x256
__device__ __nv_bfloat16 g_woh[DM*DI],   g_wol[DM*DI];     // out_proj 256x512

// ---------------- math helpers ----------------
__device__ __forceinline__ float siluf(float x) { return x / (1.0f + __expf(-x)); }
__device__ __forceinline__ float softplusf(float x) {
    return fmaxf(x, 0.0f) + log1pf(__expf(-fabsf(x)));
}
__device__ __forceinline__ void split_bf16(float v, __nv_bfloat16& h, __nv_bfloat16& l) {
    h = __float2bfloat16(v);
    l = __float2bfloat16(v - __bfloat162float(h));
}
__device__ __forceinline__ uint32_t smem_u32(const void* p) {
    uint32_t a;
    asm("{ .reg .u64 t; cvta.to.shared.u64 t, %1; cvt.u32.u64 %0, t; }" : "=r"(a) : "l"(p));
    return a;
}
#define CP_ASYNC16(dst, src, nbytes) \
    asm volatile("cp.async.cg.shared.global [%0], [%1], 16, %2;" \
                 :: "r"(dst), "l"(src), "r"(nbytes))
#define CP_COMMIT()  asm volatile("cp.async.commit_group;" ::: "memory")
#define CP_WAIT1()   asm volatile("cp.async.wait_group 1;" ::: "memory")

__device__ __forceinline__ void mma16816(float& c0, float& c1, float& c2, float& c3,
                                         uint32_t a0, uint32_t a1, uint32_t a2, uint32_t a3,
                                         uint32_t b0, uint32_t b1) {
    asm volatile("mma.sync.aligned.m16n8k16.row.col.f32.bf16.bf16.f32 "
                 "{%0,%1,%2,%3}, {%4,%5,%6,%7}, {%8,%9}, {%0,%1,%2,%3};"
                 : "+f"(c0), "+f"(c1), "+f"(c2), "+f"(c3)
                 : "r"(a0), "r"(a1), "r"(a2), "r"(a3), "r"(b0), "r"(b1));
}
__device__ __forceinline__ void ldsm_x4(uint32_t& r0, uint32_t& r1, uint32_t& r2, uint32_t& r3,
                                        uint32_t addr) {
    asm volatile("ldmatrix.sync.aligned.m8n8.x4.shared.b16 {%0,%1,%2,%3}, [%4];"
                 : "=r"(r0), "=r"(r1), "=r"(r2), "=r"(r3) : "r"(addr));
}
__device__ __forceinline__ void ldsm_x2(uint32_t& r0, uint32_t& r1, uint32_t addr) {
    asm volatile("ldmatrix.sync.aligned.m8n8.x2.shared.b16 {%0,%1}, [%2];"
                 : "=r"(r0), "=r"(r1) : "r"(addr));
}

// ---------------- 1) build seq (writes bf16 hi/lo) ----------------
__global__ void build_seq_kernel(const float* __restrict__ x,
                                 const float* __restrict__ gtok) {
    int idx = blockIdx.x * blockDim.x + threadIdx.x;
    if (idx >= MROWS * DM) return;
    int c = idx % DM;
    int l = (idx / DM) % LSEQ;
    int b = idx / (DM * LSEQ);
    float v;
    if (l == 0) {
        v = gtok[c];
    } else {
        int lp = l - 1;
        int H2 = lp / 48, W2 = lp % 48;
        int ch = c * 4 + (H2 & 1) * 2 + (W2 & 1);
        v = x[((b * 1024 + ch) * 24 + (H2 >> 1)) * 24 + (W2 >> 1)];
    }
    __nv_bfloat16 h, lo;
    split_bf16(v, h, lo);
    g_seqh[idx] = h; g_seql[idx] = lo;
}

// ---------------- weight hi/lo split ----------------
__global__ void split_kernel(const float* __restrict__ s,
                             __nv_bfloat16* __restrict__ h,
                             __nv_bfloat16* __restrict__ l, int n) {
    int i = blockIdx.x * blockDim.x + threadIdx.x;
    if (i >= n) return;
    __nv_bfloat16 hv, lv;
    split_bf16(s[i], hv, lv);
    h[i] = hv; l[i] = lv;
}

// ---------------- 2) bf16 mma.sync GEMM, single K-sweep fp32 emulation ----------------
// C[M,Ntot] = A[M,K] @ W[Ntot,K]^T, 3 MMA segments (Ah*Wh + Al*Wh + Ah*Wl)
// issued per k-chunk from 4 staged tiles (Ah, Al, Wh, Wl). CTA tile 128x128,
// 8 warps (2m x 4n), warp tile 64x32, BK=32, cp.async double buffered dynamic
// smem (80KB). GSTR=40 bf16 (80B rows): ldmatrix phase-conflict-free.
#define GSTR 40
#define TS   (128 * GSTR)            // one tile, bf16 elems
#define GEMM_SMEM (8 * TS * 2)       // 81920 bytes

template<bool FUSE_OUT>
__global__ __launch_bounds__(256, 2)
void gemm_mma_kernel(const __nv_bfloat16* __restrict__ Ah,
                     const __nv_bfloat16* __restrict__ Al,
                     const __nv_bfloat16* __restrict__ Wh,
                     const __nv_bfloat16* __restrict__ Wl,
                     float* __restrict__ C, int M, int Ntot, int K) {
    extern __shared__ __align__(16) char dsm[];
    __nv_bfloat16* sm = reinterpret_cast<__nv_bfloat16*>(dsm);
    float* xf = reinterpret_cast<float*>(dsm);   // FUSE_OUT staging (33280B)

    const int tid = threadIdx.x;
    const int wid = tid >> 5;
    const int lane = tid & 31;
    const int gr = lane >> 2;     // 0..7
    const int gc = lane & 3;      // 0..3
    const int wm = wid >> 2;      // 0..1
    const int wn = wid & 3;       // 0..3
    const int m0 = blockIdx.x * 128;
    const int n0 = blockIdx.y * 128;

    // ldmatrix lane->address components
    const int a_row = lane & 15;
    const int a_khi = (lane >> 4) * 8;
    const int b_row = lane & 7;
    const int b_khi = (lane & 8) ? 8 : 0;

    const int NC = K >> 5;        // 32-wide k-chunks

    float acc[4][4][4];
#pragma unroll
    for (int i = 0; i < 4; i++)
#pragma unroll
        for (int j = 0; j < 4; j++)
#pragma unroll
            for (int q = 0; q < 4; q++) acc[i][j][q] = 0.0f;

    // stage all 4 tiles of chunk c into buffer buf
    auto stage = [&](int c, int buf) {
        const int k0 = c * 32;
        __nv_bfloat16* base = sm + buf * 4 * TS;
        const int i = tid * 2;
        const int r  = i >> 2;            // 0..127 (row, for q=0/1 same row)
        const int s0 = (i & 3) * 8;       // 0 or 16
#pragma unroll
        for (int q = 0; q < 2; q++) {
            const int s = s0 + q * 8;
            const uint32_t so = (uint32_t)(r * GSTR + s);
            const size_t arow = (size_t)(m0 + r) * K + k0 + s;
            const size_t wrow = (size_t)(n0 + r) * K + k0 + s;
            const int aok = (m0 + r < M) ? 16 : 0;
            CP_ASYNC16(smem_u32(base + 0 * TS + so), Ah + arow, aok);
            CP_ASYNC16(smem_u32(base + 1 * TS + so), Al + arow, aok);
            CP_ASYNC16(smem_u32(base + 2 * TS + so), Wh + wrow, 16);
            CP_ASYNC16(smem_u32(base + 3 * TS + so), Wl + wrow, 16);
        }
    };

    stage(0, 0);
    CP_COMMIT();

    for (int c = 0; c < NC; c++) {
        if (c + 1 < NC) stage(c + 1, (c + 1) & 1);
        CP_COMMIT();
        CP_WAIT1();
        __syncthreads();

        const __nv_bfloat16* base = sm + (c & 1) * 4 * TS;
        const __nv_bfloat16* sAh = base;
        const __nv_bfloat16* sAl = base + TS;
        const __nv_bfloat16* sBh = base + 2 * TS;
        const __nv_bfloat16* sBl = base + 3 * TS;
#pragma unroll
        for (int ks = 0; ks < 2; ks++) {
            const int kb = ks * 16;
            uint32_t af[4][4];
            // A-hi fragments
#pragma unroll
            for (int mt = 0; mt < 4; mt++) {
                uint32_t addr = smem_u32(&sAh[(wm * 64 + mt * 16 + a_row) * GSTR + kb + a_khi]);
                ldsm_x4(af[mt][0], af[mt][1], af[mt][2], af[mt][3], addr);
            }
            // Ah*Wh and Ah*Wl
#pragma unroll
            for (int nt = 0; nt < 4; nt++) {
                const int brow = (wn * 32 + nt * 8 + b_row) * GSTR + kb + b_khi;
                uint32_t bh0, bh1, bl0, bl1;
                ldsm_x2(bh0, bh1, smem_u32(&sBh[brow]));
                ldsm_x2(bl0, bl1, smem_u32(&sBl[brow]));
#pragma unroll
                for (int mt = 0; mt < 4; mt++)
                    mma16816(acc[mt][nt][0], acc[mt][nt][1], acc[mt][nt][2], acc[mt][nt][3],
                             af[mt][0], af[mt][1], af[mt][2], af[mt][3], bh0, bh1);
#pragma unroll
                for (int mt = 0; mt < 4; mt++)
                    mma16816(acc[mt][nt][0], acc[mt][nt][1], acc[mt][nt][2], acc[mt][nt][3],
                             af[mt][0], af[mt][1], af[mt][2], af[mt][3], bl0, bl1);
            }
            // A-lo fragments (reuse af)
#pragma unroll
            for (int mt = 0; mt < 4; mt++) {
                uint32_t addr = smem_u32(&sAl[(wm * 64 + mt * 16 + a_row) * GSTR + kb + a_khi]);
                ldsm_x4(af[mt][0], af[mt][1], af[mt][2], af[mt][3], addr);
            }
            // Al*Wh
#pragma unroll
            for (int nt = 0; nt < 4; nt++) {
                const int brow = (wn * 32 + nt * 8 + b_row) * GSTR + kb + b_khi;
                uint32_t bh0, bh1;
                ldsm_x2(bh0, bh1, smem_u32(&sBh[brow]));
#pragma unroll
                for (int mt = 0; mt < 4; mt++)
                    mma16816(acc[mt][nt][0], acc[mt][nt][1], acc[mt][nt][2], acc[mt][nt][3],
                             af[mt][0], af[mt][1], af[mt][2], af[mt][3], bh0, bh1);
            }
        }
        __syncthreads();
    }

    if (!FUSE_OUT) {
#pragma unroll
        for (int mt = 0; mt < 4; mt++) {
            int r0 = m0 + wm * 64 + mt * 16 + gr;
            int r1 = r0 + 8;
#pragma unroll
            for (int nt = 0; nt < 4; nt++) {
                int n = n0 + wn * 32 + nt * 8 + gc * 2;
                if (r0 < M)
                    *reinterpret_cast<float2*>(&C[(size_t)r0 * Ntot + n]) =
                        make_float2(acc[mt][nt][0], acc[mt][nt][1]);
                if (r1 < M)
                    *reinterpret_cast<float2*>(&C[(size_t)r1 * Ntot + n]) =
                        make_float2(acc[mt][nt][2], acc[mt][nt][3]);
            }
        }
    } else {
        // coalesced pixel_unshuffle scatter via smem staging (two 64-col halves)
#pragma unroll
        for (int half = 0; half < 2; half++) {
            __syncthreads();
            if ((wn >> 1) == half) {
                int csub = wn & 1;
#pragma unroll
                for (int mt = 0; mt < 4; mt++) {
                    int rl0 = wm * 64 + mt * 16 + gr;
#pragma unroll
                    for (int nt = 0; nt < 4; nt++) {
                        int cl = csub * 32 + nt * 8 + gc * 2;
                        xf[rl0 * 65 + cl]       = acc[mt][nt][0];
                        xf[rl0 * 65 + cl + 1]   = acc[mt][nt][1];
                        xf[(rl0+8) * 65 + cl]   = acc[mt][nt][2];
                        xf[(rl0+8) * 65 + cl+1] = acc[mt][nt][3];
                    }
                }
            }
            __syncthreads();
#pragma unroll 4
            for (int it = 0; it < 32; it++) {
                int idx = it * 256 + tid;       // 128 rows x 64 cols
                int ml = idx & 127;
                int cl = idx >> 7;
                int m = m0 + ml;
                if (m < M) {
                    int b = m / LSEQ, l = m % LSEQ;
                    if (l > 0) {
                        int lp = l - 1;
                        int H2 = lp / 48, W2 = lp % 48;
                        int sub = (H2 & 1) * 2 + (W2 & 1);
                        int n = n0 + half * 64 + cl;
                        C[((b * 1024 + n * 4 + sub) * 24 + (H2 >> 1)) * 24 + (W2 >> 1)] =
                            xf[ml * 65 + cl];
                    }
                }
            }
        }
    }
}

// ---------------- 3) causal depthwise conv (k=4) + bias + silu ----------------
__global__ void conv_kernel(const float* __restrict__ conv_w,
                            const float* __restrict__ conv_b) {
    int idx = blockIdx.x * blockDim.x + threadIdx.x;
    if (idx >= MROWS * DI) return;
    int d = idx % DI;
    int l = (idx / DI) % LSEQ;
    int b = idx / (DI * LSEQ);
    float acc = conv_b[d];
#pragma unroll
    for (int k = 0; k < 4; k++) {
        int ls = l - 3 + k;
        if (ls >= 0)
            acc = fmaf(g_xz[((size_t)(b * LSEQ + ls)) * (2 * DI) + d], conv_w[d * 4 + k], acc);
    }
    g_u[(size_t)(b * LSEQ + l) * DI + d] = siluf(acc);
}

// ---------------- 4) fused x_proj (N=48) + dt projection + softplus ----------------
__global__ __launch_bounds__(256)
void xproj_dt_kernel(const float* __restrict__ xw,
                     const float* __restrict__ Wdt,
                     const float* __restrict__ bdt) {
    __shared__ union {
        struct { float As[32][32]; float Ws[32][48]; } p1;
        struct { float xs[32][48]; float wdt[16][512]; } p2;
    } sm;
    const int tid = threadIdx.x;
    const int m0 = blockIdx.x * 32;
    const int tr = tid >> 4;
    const int tc = tid & 15;

    float acc[2][3];
#pragma unroll
    for (int i = 0; i < 2; i++)
#pragma unroll
        for (int j = 0; j < 3; j++) acc[i][j] = 0.0f;

    for (int step = 0; step < 16; step++) {
        int k0 = step * 32;
        {
            int row = tid >> 3;
            int c4 = (tid & 7) * 4;
            float4 v = make_float4(0.f, 0.f, 0.f, 0.f);
            if (m0 + row < MROWS)
                v = *reinterpret_cast<const float4*>(&g_u[(size_t)(m0 + row) * DI + k0 + c4]);
            sm.p1.As[c4+0][row] = v.x; sm.p1.As[c4+1][row] = v.y;
            sm.p1.As[c4+2][row] = v.z; sm.p1.As[c4+3][row] = v.w;
        }
        for (int t = tid; t < 384; t += 256) {
            int n = t >> 3;
            int c4 = (t & 7) * 4;
            float4 v = *reinterpret_cast<const float4*>(&xw[(size_t)n * DI + k0 + c4]);
            sm.p1.Ws[c4+0][n] = v.x; sm.p1.Ws[c4+1][n] = v.y;
            sm.p1.Ws[c4+2][n] = v.z; sm.p1.Ws[c4+3][n] = v.w;
        }
        __syncthreads();
#pragma unroll
        for (int k = 0; k < 32; k++) {
            float a0 = sm.p1.As[k][tr * 2 + 0];
            float a1 = sm.p1.As[k][tr * 2 + 1];
            float b0 = sm.p1.Ws[k][tc*3+0];
            float b1 = sm.p1.Ws[k][tc*3+1];
            float b2 = sm.p1.Ws[k][tc*3+2];
            acc[0][0] = fmaf(a0, b0, acc[0][0]);
            acc[0][1] = fmaf(a0, b1, acc[0][1]);
            acc[0][2] = fmaf(a0, b2, acc[0][2]);
            acc[1][0] = fmaf(a1, b0, acc[1][0]);
            acc[1][1] = fmaf(a1, b1, acc[1][1]);
            acc[1][2] = fmaf(a1, b2, acc[1][2]);
        }
        __syncthreads();
    }

#pragma unroll
    for (int i = 0; i < 2; i++) {
        int m = m0 + tr * 2 + i;
#pragma unroll
        for (int j = 0; j < 3; j++) {
            int n = tc * 3 + j;
            sm.p2.xs[tr * 2 + i][n] = acc[i][j];
            if (m < MROWS) g_xdbl[(size_t)m * NDBL + n] = acc[i][j];
        }
    }
    for (int t = tid; t < DI * DTR; t += 256) {
        int d = t >> 4, k = t & 15;
        sm.p2.wdt[k][d] = Wdt[t];
    }
    __syncthreads();

    const int d0 = tid * 2;
    float wr0[16], wr1[16];
#pragma unroll
    for (int k = 0; k < 16; k++) { wr0[k] = sm.p2.wdt[k][d0]; wr1[k] = sm.p2.wdt[k][d0+1]; }
    const float b0 = bdt[d0], b1 = bdt[d0+1];
    for (int row = 0; row < 32; row++) {
        int m = m0 + row;
        if (m >= MROWS) break;
        float a0 = b0, a1 = b1;
#pragma unroll
        for (int k = 0; k < 16; k++) {
            float xv = sm.p2.xs[row][k];
            a0 = fmaf(xv, wr0[k], a0);
            a1 = fmaf(xv, wr1[k], a1);
        }
        float2 o = make_float2(softplusf(a0), softplusf(a1));
        *reinterpret_cast<float2*>(&g_dt[(size_t)m * DI + d0]) = o;
    }
}

// ---------------- power-chain dA helper ----------------
__device__ __forceinline__ void da_powers(float e1, float dA[DS]) {
    float e2 = e1 * e1;
    float e4 = e2 * e2;
    float e8 = e4 * e4;
    dA[0]=e1;        dA[1]=e2;        dA[2]=e2*e1;     dA[3]=e4;
    dA[4]=e4*e1;     dA[5]=e4*e2;     dA[6]=e4*e2*e1;  dA[7]=e8;
    dA[8]=e8*e1;     dA[9]=e8*e2;     dA[10]=e8*e2*e1; dA[11]=e8*e4;
    dA[12]=e8*e4*e1; dA[13]=e8*e4*e2; dA[14]=e8*e4*e2*e1; dA[15]=e8*e8;
}

// ---------------- 5) scan pass 1 ----------------
__global__ void scan_pass1_kernel(const float* __restrict__ A_log) {
    int d = blockIdx.x * 128 + threadIdx.x;
    int c = blockIdx.y;
    int b = blockIdx.z;
    float Aa[DS], h[DS], P[DS];
    bool chain = true;
#pragma unroll
    for (int n = 0; n < DS; n++) {
        Aa[n] = -__expf(A_log[d * DS + n]);
        h[n] = 0.0f; P[n] = 1.0f;
    }
    float a1 = Aa[0];
#pragma unroll
    for (int n = 0; n < DS; n++)
        chain = chain && (fabsf(Aa[n] - a1 * (n + 1)) < 1e-3f * (n + 1));

    int l0 = c * CHUNK;
    int l1 = min(LSEQ, l0 + CHUNK);
    for (int l = l0; l < l1; l++) {
        size_t row = (size_t)b * LSEQ + l;
        float dtv = g_dt[row * DI + d];
        float uv  = g_u [row * DI + d];
        float du  = dtv * uv;
        const float4* Bp = reinterpret_cast<const float4*>(&g_xdbl[row * NDBL + DTR]);
        float4 t0 = Bp[0], t1 = Bp[1], t2 = Bp[2], t3 = Bp[3];
        float Bv[DS] = {t0.x, t0.y, t0.z, t0.w, t1.x, t1.y, t1.z, t1.w,
                        t2.x, t2.y, t2.z, t2.w, t3.x, t3.y, t3.z, t3.w};
        float dA[DS];
        if (chain) {
            da_powers(__expf(dtv * a1), dA);
        } else {
#pragma unroll
            for (int n = 0; n < DS; n++) dA[n] = __expf(dtv * Aa[n]);
        }
#pragma unroll
        for (int n = 0; n < DS; n++) {
            P[n] *= dA[n];
            h[n] = fmaf(dA[n], h[n], du * Bv[n]);
        }
    }
    size_t base = (((size_t)b * DI + d) * NCHUNK + c) * DS;
#pragma unroll
    for (int n = 0; n < DS; n++) { g_P[base + n] = P[n]; g_hf[base + n] = h[n]; }
}

// ---------------- 6) sequential combine ----------------
__global__ void scan_combine_kernel() {
    int idx = blockIdx.x * blockDim.x + threadIdx.x;
    if (idx >= BATCH * DI * DS) return;
    int n = idx % DS;
    int d = (idx / DS) % DI;
    int b = idx / (DS * DI);
    float h = 0.0f;
    for (int c = 0; c < NCHUNK; c++) {
        size_t base = (((size_t)b * DI + d) * NCHUNK + c) * DS + n;
        g_hin[base] = h;
        h = fmaf(g_P[base], h, g_hf[base]);
    }
}

// ---------------- 7) scan pass 2 + gating, writes bf16 hi/lo y ----------------
__global__ void scan_pass2_kernel(const float* __restrict__ A_log,
                                  const float* __restrict__ Dp) {
    int d = blockIdx.x * 128 + threadIdx.x;
    int c = blockIdx.y;
    int b = blockIdx.z;
    float Aa[DS], h[DS];
    size_t hbase = (((size_t)b * DI + d) * NCHUNK + c) * DS;
    bool chain = true;
#pragma unroll
    for (int n = 0; n < DS; n++) {
        Aa[n] = -__expf(A_log[d * DS + n]);
        h[n] = g_hin[hbase + n];
    }
    float a1 = Aa[0];
#pragma unroll
    for (int n = 0; n < DS; n++)
        chain = chain && (fabsf(Aa[n] - a1 * (n + 1)) < 1e-3f * (n + 1));

    float Dd = Dp[d];
    int l0 = c * CHUNK;
    int l1 = min(LSEQ, l0 + CHUNK);
    for (int l = l0; l < l1; l++) {
        size_t row = (size_t)b * LSEQ + l;
        float dtv = g_dt[row * DI + d];
        float uv  = g_u [row * DI + d];
        float du  = dtv * uv;
        const float4* BCp = reinterpret_cast<const float4*>(&g_xdbl[row * NDBL + DTR]);
        float4 t0 = BCp[0], t1 = BCp[1], t2 = BCp[2], t3 = BCp[3];
        float4 t4 = BCp[4], t5 = BCp[5], t6 = BCp[6], t7 = BCp[7];
        float Bv[DS] = {t0.x, t0.y, t0.z, t0.w, t1.x, t1.y, t1.z, t1.w,
                        t2.x, t2.y, t2.z, t2.w, t3.x, t3.y, t3.z, t3.w};
        float Cv[DS] = {t4.x, t4.y, t4.z, t4.w, t5.x, t5.y, t5.z, t5.w,
                        t6.x, t6.y, t6.z, t6.w, t7.x, t7.y, t7.z, t7.w};
        float dA[DS];
        if (chain) {
            da_powers(__expf(dtv * a1), dA);
        } else {
#pragma unroll
            for (int n = 0; n < DS; n++) dA[n] = __expf(dtv * Aa[n]);
        }
        float y = 0.0f;
#pragma unroll
        for (int n = 0; n < DS; n++) {
            h[n] = fmaf(dA[n], h[n], du * Bv[n]);
            y = fmaf(h[n], Cv[n], y);
        }
        float z = g_xz[row * (2 * DI) + DI + d];
        float yv = (y + uv * Dd) * siluf(z);
        __nv_bfloat16 hh, ll;
        split_bf16(yv, hh, ll);
        g_yh[row * DI + d] = hh;
        g_yl[row * DI + d] = ll;
    }
}

// ---------------- launch ----------------
extern "C" void kernel_launch(void* const* d_in, const int* in_sizes, int n_in,
                              void* d_out, int out_size) {
    const float* x          = (const float*)d_in[0];
    const float* gtok       = (const float*)d_in[1];
    const float* in_proj_w  = (const float*)d_in[2];
    const float* conv_w     = (const float*)d_in[3];
    const float* conv_b     = (const float*)d_in[4];
    const float* x_proj_w   = (const float*)d_in[5];
    const float* dt_proj_w  = (const float*)d_in[6];
    const float* dt_proj_b  = (const float*)d_in[7];
    const float* A_log      = (const float*)d_in[8];
    const float* Dp         = (const float*)d_in[9];
    const float* out_proj_w = (const float*)d_in[10];
    float* out = (float*)d_out;

    float *p_xz;
    __nv_bfloat16 *p_seqh, *p_seql, *p_yh, *p_yl, *p_wih, *p_wil, *p_woh, *p_wol;
    cudaGetSymbolAddress((void**)&p_xz,   g_xz);
    cudaGetSymbolAddress((void**)&p_seqh, g_seqh);
    cudaGetSymbolAddress((void**)&p_seql, g_seql);
    cudaGetSymbolAddress((void**)&p_yh,   g_yh);
    cudaGetSymbolAddress((void**)&p_yl,   g_yl);
    cudaGetSymbolAddress((void**)&p_wih,  g_wih);
    cudaGetSymbolAddress((void**)&p_wil,  g_wil);
    cudaGetSymbolAddress((void**)&p_woh,  g_woh);
    cudaGetSymbolAddress((void**)&p_wol,  g_wol);

    cudaFuncSetAttribute(gemm_mma_kernel<false>,
                         cudaFuncAttributeMaxDynamicSharedMemorySize, GEMM_SMEM);
    cudaFuncSetAttribute(gemm_mma_kernel<true>,
                         cudaFuncAttributeMaxDynamicSharedMemorySize, GEMM_SMEM);

    // 1. seq (bf16 hi/lo) + weight splits
    build_seq_kernel<<<(MROWS * DM + 255) / 256, 256>>>(x, gtok);
    split_kernel<<<(2 * DI * DM + 255) / 256, 256>>>(in_proj_w, p_wih, p_wil, 2 * DI * DM);
    split_kernel<<<(DM * DI + 255) / 256, 256>>>(out_proj_w, p_woh, p_wol, DM * DI);

    // 2. xz = seq @ in_proj_w^T  (single-sweep bf16x3 mma.sync)
    {
        dim3 grid((MROWS + 127) / 128, (2 * DI) / 128);
        gemm_mma_kernel<false><<<grid, 256, GEMM_SMEM>>>(p_seqh, p_seql, p_wih, p_wil,
                                                         p_xz, MROWS, 2 * DI, DM);
    }

    // 3. u = silu(causal_conv(xz[:, :512]) + b)
    conv_kernel<<<(MROWS * DI + 255) / 256, 256>>>(conv_w, conv_b);

    // 4+5. x_dbl + dt (fused)
    xproj_dt_kernel<<<(MROWS + 31) / 32, 256>>>(x_proj_w, dt_proj_w, dt_proj_b);

    // 6-8. chunked selective scan + gating
    {
        dim3 grid(DI / 128, NCHUNK, BATCH);
        scan_pass1_kernel<<<grid, 128>>>(A_log);
        scan_combine_kernel<<<(BATCH * DI * DS + 255) / 256, 256>>>();
        scan_pass2_kernel<<<grid, 128>>>(A_log, Dp);
    }

    // 9. out = y @ out_proj_w^T (fused coalesced pixel_unshuffle)
    {
        dim3 grid((MROWS + 127) / 128, DM / 128);
        gemm_mma_kernel<true><<<grid, 256, GEMM_SMEM>>>(p_yh, p_yl, p_woh, p_wol,
                                                        out, MROWS, DM, DI);
    }
}